// round 2
// baseline (speedup 1.0000x reference)
#include <cuda_runtime.h>
#include <cuda_bf16.h>
#include <math.h>

// Problem constants
#define BATCH 32
#define LSEQ  128
#define TSTEPS 127          // L-1
#define HDIM  512
#define VOCAB 8000
#define NHEADS 8
#define HEADD 64
#define SKEYS 256
#define G4    2048          // 4*H
#define MROWS (BATCH*TSTEPS)   // 4064
#define ENCROWS (BATCH*SKEYS)  // 8192

#define LSTM_NBLK 128       // persistent blocks (<=148 SMs, all co-resident)
#define HD_PER_BLK 4        // 512 / 128

// ------------------------- scratch (device globals) -------------------------
__device__ float d_emb [MROWS * HDIM];
__device__ float d_xg  [MROWS * G4];
__device__ float d_hbuf[2 * BATCH * HDIM];
__device__ float d_hs  [MROWS * HDIM];
__device__ float d_q   [MROWS * HDIM];
__device__ float d_k   [ENCROWS * HDIM];
__device__ float d_v   [ENCROWS * HDIM];
__device__ float d_ctx [MROWS * HDIM];
__device__ float d_comb[MROWS * HDIM];
__device__ int   d_bar [TSTEPS];

// ------------------------- embedding gather (+ barrier-counter reset) ------
__global__ void gather_embed_kernel(const int* __restrict__ targets,
                                    const float* __restrict__ embedding,
                                    float* __restrict__ emb,
                                    int* __restrict__ bar) {
    int idx = blockIdx.x * blockDim.x + threadIdx.x;
    if (idx < TSTEPS) bar[idx] = 0;
    if (idx >= MROWS * HDIM) return;
    int hh = idx & (HDIM - 1);
    int bt = idx >> 9;
    int b = bt / TSTEPS;
    int t = bt - b * TSTEPS;
    int tok = targets[b * LSEQ + t];
    emb[idx] = embedding[(size_t)tok * HDIM + hh];
}

// ------------------------- generic SGEMM: C = A @ B^T (+bias0+bias1+add) ----
__global__ __launch_bounds__(256)
void sgemm_tn_kernel(const float* __restrict__ A, const float* __restrict__ B,
                     const float* __restrict__ bias0, const float* __restrict__ bias1,
                     const float* __restrict__ addsrc, float* __restrict__ C,
                     int M, int N, int K) {
    __shared__ float As[16 * 132];
    __shared__ float Bs[16 * 132];
    int tid = threadIdx.x;
    int bm = blockIdx.y, bn = blockIdx.x;
    int tx = tid & 15, ty = tid >> 4;
    int arow_base = bm * 128, bcol_base = bn * 128;

    float acc[8][8];
#pragma unroll
    for (int i = 0; i < 8; i++)
#pragma unroll
        for (int j = 0; j < 8; j++) acc[i][j] = 0.f;

    for (int k0 = 0; k0 < K; k0 += 16) {
#pragma unroll
        for (int i = 0; i < 2; i++) {
            int f = tid + i * 256;
            int r = f >> 2, kq = (f & 3) << 2;
            int grow = arow_base + r;
            float4 v = make_float4(0.f, 0.f, 0.f, 0.f);
            if (grow < M) v = *(const float4*)(A + (size_t)grow * K + k0 + kq);
            As[(kq + 0) * 132 + r] = v.x;
            As[(kq + 1) * 132 + r] = v.y;
            As[(kq + 2) * 132 + r] = v.z;
            As[(kq + 3) * 132 + r] = v.w;
        }
#pragma unroll
        for (int i = 0; i < 2; i++) {
            int f = tid + i * 256;
            int r = f >> 2, kq = (f & 3) << 2;
            int grow = bcol_base + r;
            float4 v = make_float4(0.f, 0.f, 0.f, 0.f);
            if (grow < N) v = *(const float4*)(B + (size_t)grow * K + k0 + kq);
            Bs[(kq + 0) * 132 + r] = v.x;
            Bs[(kq + 1) * 132 + r] = v.y;
            Bs[(kq + 2) * 132 + r] = v.z;
            Bs[(kq + 3) * 132 + r] = v.w;
        }
        __syncthreads();
#pragma unroll
        for (int kk = 0; kk < 16; kk++) {
            float a[8], bv[8];
            float4 a0 = *(const float4*)&As[kk * 132 + ty * 8];
            float4 a1 = *(const float4*)&As[kk * 132 + ty * 8 + 4];
            float4 b0 = *(const float4*)&Bs[kk * 132 + tx * 8];
            float4 b1 = *(const float4*)&Bs[kk * 132 + tx * 8 + 4];
            a[0]=a0.x; a[1]=a0.y; a[2]=a0.z; a[3]=a0.w; a[4]=a1.x; a[5]=a1.y; a[6]=a1.z; a[7]=a1.w;
            bv[0]=b0.x; bv[1]=b0.y; bv[2]=b0.z; bv[3]=b0.w; bv[4]=b1.x; bv[5]=b1.y; bv[6]=b1.z; bv[7]=b1.w;
#pragma unroll
            for (int i = 0; i < 8; i++)
#pragma unroll
                for (int j = 0; j < 8; j++) acc[i][j] += a[i] * bv[j];
        }
        __syncthreads();
    }

#pragma unroll
    for (int i = 0; i < 8; i++) {
        int row = arow_base + ty * 8 + i;
        if (row >= M) continue;
#pragma unroll
        for (int j = 0; j < 8; j++) {
            int col = bcol_base + tx * 8 + j;
            if (col >= N) continue;
            float v = acc[i][j];
            if (bias0) v += bias0[col];
            if (bias1) v += bias1[col];
            if (addsrc) v += addsrc[(size_t)row * N + col];
            C[(size_t)row * N + col] = v;
        }
    }
}

// ------------------------- persistent LSTM scan ----------------------------
// ONE launch for all 127 steps. 128 blocks x 128 threads (all co-resident).
// Block owns HD_PER_BLK=4 hidden units (16 w_hh rows), staged in smem ONCE.
// warp <-> hidden unit, lane <-> batch. c-state lives in a register.
// h double-buffered in global; custom grid barrier (counter per step).
#define HSTRIDE 516   // 516 % 32 == 4 -> conflict-free LDS.128 across lanes

__global__ __launch_bounds__(128, 1)
void lstm_persist_kernel(const float* __restrict__ w_hh,
                         const float* __restrict__ xg,
                         float* __restrict__ hbuf,
                         float* __restrict__ hs,
                         int* __restrict__ bar) {
    extern __shared__ float sm[];
    float* ws  = sm;                    // [16][512]  32 KB
    float* hsm = sm + 16 * 512;         // [32][HSTRIDE] ~66 KB

    int tid  = threadIdx.x;
    int warp = tid >> 5;                // 0..3 -> hidden unit
    int lane = tid & 31;                // batch
    int hd0  = blockIdx.x * HD_PER_BLK;
    int hd   = hd0 + warp;

    // stage weights once: local row (hd_l*4 + g) <- w_hh[g*512 + hd0 + hd_l]
    for (int idx = tid; idx < 16 * 512; idx += 128) {
        int lr = idx >> 9;
        int k  = idx & 511;
        int hd_l = lr >> 2, g = lr & 3;
        ws[lr * 512 + k] = w_hh[((size_t)(g * HDIM + hd0 + hd_l)) * HDIM + k];
    }

    const float* wp = ws + warp * 4 * 512;      // 4 gate rows for this hd
    const float* hp = hsm + lane * HSTRIDE;
    float c_reg = 0.f;
    size_t xg_base = ((size_t)lane * TSTEPS) * G4 + hd;   // + t*G4 + g*512

    for (int t = 0; t < TSTEPS; t++) {
        const float* hcur = hbuf + (t & 1) * (BATCH * HDIM);
        float*       hnxt = hbuf + ((t + 1) & 1) * (BATCH * HDIM);

        // prefetch xg for this step (scattered; issue early)
        size_t xb = xg_base + (size_t)t * G4;
        float xgi = __ldg(xg + xb);
        float xgf = __ldg(xg + xb + 512);
        float xgg = __ldg(xg + xb + 1024);
        float xgo = __ldg(xg + xb + 1536);

        if (t > 0) {
            // stage h into smem: coalesced global read, conflict-free smem write
            for (int idx = tid; idx < BATCH * HDIM / 4; idx += 128) {
                int b  = idx >> 7;          // /128 float4 per batch row
                int k4 = idx & 127;
                float4 v = ((const float4*)hcur)[idx];
                *(float4*)&hsm[b * HSTRIDE + k4 * 4] = v;
            }
        }
        __syncthreads();

        float ai = 0.f, af = 0.f, ag = 0.f, ao = 0.f;
        if (t > 0) {
#pragma unroll 4
            for (int k4 = 0; k4 < 128; k4++) {
                float4 hv = *(const float4*)(hp + k4 * 4);
                float4 w0 = *(const float4*)(wp + k4 * 4);
                float4 w1 = *(const float4*)(wp + 512 + k4 * 4);
                float4 w2 = *(const float4*)(wp + 1024 + k4 * 4);
                float4 w3 = *(const float4*)(wp + 1536 + k4 * 4);
                ai += w0.x * hv.x + w0.y * hv.y + w0.z * hv.z + w0.w * hv.w;
                af += w1.x * hv.x + w1.y * hv.y + w1.z * hv.z + w1.w * hv.w;
                ag += w2.x * hv.x + w2.y * hv.y + w2.z * hv.z + w2.w * hv.w;
                ao += w3.x * hv.x + w3.y * hv.y + w3.z * hv.z + w3.w * hv.w;
            }
        }
        float i_ = 1.f / (1.f + expf(-(ai + xgi)));
        float f_ = 1.f / (1.f + expf(-(af + xgf)));
        float g_ = tanhf(ag + xgg);
        float o_ = 1.f / (1.f + expf(-(ao + xgo)));
        c_reg = f_ * c_reg + i_ * g_;
        float hn = o_ * tanhf(c_reg);

        hnxt[lane * HDIM + hd] = hn;
        hs[((size_t)(lane * TSTEPS + t)) * HDIM + hd] = hn;

        if (t < TSTEPS - 1) {
            __threadfence();            // release h writes
            __syncthreads();            // all warps in block done
            if (tid == 0) {
                atomicAdd(&bar[t], 1);
                while (*(volatile int*)&bar[t] < LSTM_NBLK) { }
            }
            __syncthreads();
            __threadfence();            // acquire before next stage-in
        }
    }
}

// ------------------------- fused attention ---------------------------------
__global__ __launch_bounds__(256)
void attn_kernel(const float* __restrict__ q, const float* __restrict__ kb,
                 const float* __restrict__ vb, float* __restrict__ ctx) {
    extern __shared__ float sm[];
    float* Ks = sm;                  // 256*65
    float* Vs = Ks + 256 * 65;       // 256*65
    float* qs = Vs + 256 * 65;       // 8*64
    float* ps = qs + 8 * 64;         // 8*256
    int tid = threadIdx.x;
    int b = blockIdx.x >> 3, hh = blockIdx.x & 7;
    const float* kbase = kb + (size_t)b * SKEYS * HDIM + hh * HEADD;
    const float* vbase = vb + (size_t)b * SKEYS * HDIM + hh * HEADD;

    for (int idx = tid; idx < SKEYS * HEADD; idx += 256) {
        int s = idx >> 6, d = idx & 63;
        Ks[s * 65 + d] = kbase[(size_t)s * HDIM + d];
        Vs[s * 65 + d] = vbase[(size_t)s * HDIM + d];
    }
    __syncthreads();

    int w = tid >> 5, l = tid & 31;
    for (int q0 = 0; q0 < TSTEPS; q0 += 8) {
        for (int idx = tid; idx < 8 * HEADD; idx += 256) {
            int qi = idx >> 6, d = idx & 63;
            int qq = q0 + qi;
            qs[idx] = (qq < TSTEPS) ? q[(size_t)(b * TSTEPS + qq) * HDIM + hh * HEADD + d] : 0.f;
        }
        __syncthreads();
        int qq = q0 + w;
        if (qq < TSTEPS) {
            float sc[8];
#pragma unroll
            for (int ki = 0; ki < 8; ki++) {
                int s = l + (ki << 5);
                float dot = 0.f;
#pragma unroll
                for (int d = 0; d < HEADD; d++)
                    dot += qs[w * 64 + d] * Ks[s * 65 + d];
                sc[ki] = dot * 0.125f;
            }
            float m = sc[0];
#pragma unroll
            for (int ki = 1; ki < 8; ki++) m = fmaxf(m, sc[ki]);
#pragma unroll
            for (int o = 16; o > 0; o >>= 1) m = fmaxf(m, __shfl_xor_sync(0xffffffffu, m, o));
            float sum = 0.f;
#pragma unroll
            for (int ki = 0; ki < 8; ki++) { sc[ki] = expf(sc[ki] - m); sum += sc[ki]; }
#pragma unroll
            for (int o = 16; o > 0; o >>= 1) sum += __shfl_xor_sync(0xffffffffu, sum, o);
            float inv = 1.f / sum;
#pragma unroll
            for (int ki = 0; ki < 8; ki++) ps[w * 256 + l + (ki << 5)] = sc[ki] * inv;
            __syncwarp();
            float a0 = 0.f, a1 = 0.f;
#pragma unroll 4
            for (int s = 0; s < SKEYS; s++) {
                float pw = ps[w * 256 + s];
                a0 += pw * Vs[s * 65 + l];
                a1 += pw * Vs[s * 65 + l + 32];
            }
            size_t obase = (size_t)(b * TSTEPS + qq) * HDIM + hh * HEADD;
            ctx[obase + l] = a0;
            ctx[obase + l + 32] = a1;
        }
        __syncthreads();
    }
}

// ------------------------- launch ------------------------------------------
static const int ATTN_SMEM = (2 * 256 * 65 + 8 * 64 + 8 * 256) * (int)sizeof(float);
static const int LSTM_SMEM = (16 * 512 + 32 * HSTRIDE) * (int)sizeof(float);

extern "C" void kernel_launch(void* const* d_in, const int* in_sizes, int n_in,
                              void* d_out, int out_size) {
    const int*   targets    = (const int*)  d_in[0];
    const float* enc        = (const float*)d_in[1];
    const float* embedding  = (const float*)d_in[2];
    const float* w_ih       = (const float*)d_in[3];
    const float* w_hh       = (const float*)d_in[4];
    const float* b_ih       = (const float*)d_in[5];
    const float* b_hh       = (const float*)d_in[6];
    const float* in_proj_w  = (const float*)d_in[7];
    const float* in_proj_b  = (const float*)d_in[8];
    const float* out_proj_w = (const float*)d_in[9];
    const float* out_proj_b = (const float*)d_in[10];
    const float* fc_w       = (const float*)d_in[11];
    const float* fc_b       = (const float*)d_in[12];
    float* out = (float*)d_out;

    float *emb, *xg, *hbuf, *hs, *qb, *kk, *vv, *ctx, *comb;
    int* bar;
    cudaGetSymbolAddress((void**)&emb,  d_emb);
    cudaGetSymbolAddress((void**)&xg,   d_xg);
    cudaGetSymbolAddress((void**)&hbuf, d_hbuf);
    cudaGetSymbolAddress((void**)&hs,   d_hs);
    cudaGetSymbolAddress((void**)&qb,   d_q);
    cudaGetSymbolAddress((void**)&kk,   d_k);
    cudaGetSymbolAddress((void**)&vv,   d_v);
    cudaGetSymbolAddress((void**)&ctx,  d_ctx);
    cudaGetSymbolAddress((void**)&comb, d_comb);
    cudaGetSymbolAddress((void**)&bar,  d_bar);

    cudaFuncSetAttribute(attn_kernel, cudaFuncAttributeMaxDynamicSharedMemorySize, ATTN_SMEM);
    cudaFuncSetAttribute(lstm_persist_kernel, cudaFuncAttributeMaxDynamicSharedMemorySize, LSTM_SMEM);

    // 1. embedding gather (+ zero the barrier counters)
    {
        int n = MROWS * HDIM;
        gather_embed_kernel<<<(n + 255) / 256, 256>>>(targets, embedding, emb, bar);
    }
    // 2. xg = emb @ w_ih^T + b_ih + b_hh
    {
        dim3 grid(G4 / 128, (MROWS + 127) / 128);
        sgemm_tn_kernel<<<grid, 256>>>(emb, w_ih, b_ih, b_hh, nullptr, xg, MROWS, G4, HDIM);
    }
    // 3. full LSTM scan: ONE persistent launch
    lstm_persist_kernel<<<LSTM_NBLK, 128, LSTM_SMEM>>>(w_hh, xg, hbuf, hs, bar);
    // 4. q projection
    {
        dim3 grid(HDIM / 128, (MROWS + 127) / 128);
        sgemm_tn_kernel<<<grid, 256>>>(hs, in_proj_w, in_proj_b, nullptr, nullptr, qb, MROWS, HDIM, HDIM);
    }
    // 5. k projection
    {
        dim3 grid(HDIM / 128, ENCROWS / 128);
        sgemm_tn_kernel<<<grid, 256>>>(enc, in_proj_w + (size_t)HDIM * HDIM,
                                       in_proj_b + HDIM, nullptr, nullptr, kk, ENCROWS, HDIM, HDIM);
    }
    // 6. v projection
    {
        dim3 grid(HDIM / 128, ENCROWS / 128);
        sgemm_tn_kernel<<<grid, 256>>>(enc, in_proj_w + (size_t)2 * HDIM * HDIM,
                                       in_proj_b + 2 * HDIM, nullptr, nullptr, vv, ENCROWS, HDIM, HDIM);
    }
    // 7. attention
    attn_kernel<<<BATCH * NHEADS, 256, ATTN_SMEM>>>(qb, kk, vv, ctx);
    // 8. out projection + residual (lstm_out)
    {
        dim3 grid(HDIM / 128, (MROWS + 127) / 128);
        sgemm_tn_kernel<<<grid, 256>>>(ctx, out_proj_w, out_proj_b, nullptr, hs, comb, MROWS, HDIM, HDIM);
    }
    // 9. fc
    {
        dim3 grid((VOCAB + 127) / 128, (MROWS + 127) / 128);
        sgemm_tn_kernel<<<grid, 256>>>(comb, fc_w, fc_b, nullptr, nullptr, out, MROWS, VOCAB, HDIM);
    }
}

// round 4
// speedup vs baseline: 1.2265x; 1.2265x over previous
#include <cuda_runtime.h>
#include <cuda_bf16.h>
#include <math.h>
#include <stdint.h>

// Problem constants
#define BATCH 32
#define LSEQ  128
#define TSTEPS 127          // L-1
#define HDIM  512
#define VOCAB 8000
#define NHEADS 8
#define HEADD 64
#define SKEYS 256
#define G4    2048          // 4*H
#define MROWS (BATCH*TSTEPS)   // 4064
#define ENCROWS (BATCH*SKEYS)  // 8192

#define LSTM_NBLK 128
#define HD_PER_BLK 4

// ------------------------- scratch (device globals) -------------------------
__device__ float d_emb [MROWS * HDIM];
__device__ float d_xg  [MROWS * G4];
__device__ float d_hbuf[2 * BATCH * HDIM];
__device__ float d_hs  [MROWS * HDIM];
__device__ float d_q   [MROWS * HDIM];
__device__ float d_kv  [ENCROWS * 2 * HDIM];   // k|v interleaved per row (stride 1024)
__device__ float d_ctx [MROWS * HDIM];
__device__ float d_comb[MROWS * HDIM];
__device__ int   d_bar [TSTEPS];

// ------------------------- embedding gather (+ barrier reset) --------------
__global__ void gather_embed_kernel(const int* __restrict__ targets,
                                    const float* __restrict__ embedding,
                                    float* __restrict__ emb,
                                    int* __restrict__ bar) {
    int idx = blockIdx.x * blockDim.x + threadIdx.x;
    if (idx < TSTEPS) bar[idx] = 0;
    if (idx >= MROWS * HDIM) return;
    int hh = idx & (HDIM - 1);
    int bt = idx >> 9;
    int b = bt / TSTEPS;
    int t = bt - b * TSTEPS;
    int tok = targets[b * LSEQ + t];
    emb[idx] = embedding[(size_t)tok * HDIM + hh];
}

// ------------------------- split-bf16 tensor-core GEMM ---------------------
// C[M,N] = A[M,K] @ B[N,K]^T (+bias0+bias1+add), fp32 I/O.
// Compute: A,B split into hi+lo bf16; acc = Ah*Bh + Ah*Bl + Al*Bh (fp32 mma).
// Block 128x128x32, 8 warps (2x4), warp tile 64x32, m16n8k16 mma.
#define BM 128
#define BN 128
#define BK 32
#define ASTR 40   // bf16 units per smem row (conflict-free fragment loads)

__device__ __forceinline__ void mma16816(float* c, const uint32_t a[4], const uint32_t b[2]) {
    asm volatile(
        "mma.sync.aligned.m16n8k16.row.col.f32.bf16.bf16.f32 "
        "{%0,%1,%2,%3}, {%4,%5,%6,%7}, {%8,%9}, {%0,%1,%2,%3};"
        : "+f"(c[0]), "+f"(c[1]), "+f"(c[2]), "+f"(c[3])
        : "r"(a[0]), "r"(a[1]), "r"(a[2]), "r"(a[3]), "r"(b[0]), "r"(b[1]));
}

__global__ __launch_bounds__(256)
void bgemm_tn_kernel(const float* __restrict__ A, const float* __restrict__ B,
                     const float* __restrict__ bias0, const float* __restrict__ bias1,
                     const float* __restrict__ addsrc, float* __restrict__ C,
                     int M, int N, int K) {
    __shared__ __nv_bfloat16 Ah[BM * ASTR];
    __shared__ __nv_bfloat16 Al[BM * ASTR];
    __shared__ __nv_bfloat16 Bh[BN * ASTR];
    __shared__ __nv_bfloat16 Bl[BN * ASTR];

    int tid = threadIdx.x;
    int m0 = blockIdx.y * BM, n0 = blockIdx.x * BN;
    int warp = tid >> 5, lane = tid & 31;
    int wm = (warp >> 2) * 64;      // warp M offset within block
    int wn = (warp & 3) * 32;       // warp N offset
    int g  = lane >> 2;             // group id (0..7)
    int t4 = lane & 3;              // thread-in-group

    float acc[4][4][4];
#pragma unroll
    for (int i = 0; i < 4; i++)
#pragma unroll
        for (int j = 0; j < 4; j++) {
            acc[i][j][0] = 0.f; acc[i][j][1] = 0.f; acc[i][j][2] = 0.f; acc[i][j][3] = 0.f;
        }

    for (int k0 = 0; k0 < K; k0 += BK) {
        // stage A tile (128x32 floats -> hi/lo bf16)
#pragma unroll
        for (int i = 0; i < 4; i++) {
            int idx = tid + i * 256;
            int r = idx >> 3, kq = (idx & 7) << 2;
            float4 v = make_float4(0.f, 0.f, 0.f, 0.f);
            int grow = m0 + r;
            if (grow < M) v = *(const float4*)(A + (size_t)grow * K + k0 + kq);
            float vs[4] = {v.x, v.y, v.z, v.w};
#pragma unroll
            for (int j = 0; j < 4; j++) {
                __nv_bfloat16 h = __float2bfloat16_rn(vs[j]);
                __nv_bfloat16 l = __float2bfloat16_rn(vs[j] - __bfloat162float(h));
                Ah[r * ASTR + kq + j] = h;
                Al[r * ASTR + kq + j] = l;
            }
        }
        // stage B tile (128x32)
#pragma unroll
        for (int i = 0; i < 4; i++) {
            int idx = tid + i * 256;
            int r = idx >> 3, kq = (idx & 7) << 2;
            float4 v = make_float4(0.f, 0.f, 0.f, 0.f);
            int grow = n0 + r;
            if (grow < N) v = *(const float4*)(B + (size_t)grow * K + k0 + kq);
            float vs[4] = {v.x, v.y, v.z, v.w};
#pragma unroll
            for (int j = 0; j < 4; j++) {
                __nv_bfloat16 h = __float2bfloat16_rn(vs[j]);
                __nv_bfloat16 l = __float2bfloat16_rn(vs[j] - __bfloat162float(h));
                Bh[r * ASTR + kq + j] = h;
                Bl[r * ASTR + kq + j] = l;
            }
        }
        __syncthreads();

#pragma unroll
        for (int ko = 0; ko < BK; ko += 16) {
            uint32_t af[4][4], bh[4][2], bl[4][2];
            int ca = ko + t4 * 2;
            // load B hi + lo fragments
#pragma unroll
            for (int nt = 0; nt < 4; nt++) {
                int n = wn + nt * 8 + g;
                bh[nt][0] = *(const uint32_t*)&Bh[n * ASTR + ca];
                bh[nt][1] = *(const uint32_t*)&Bh[n * ASTR + ca + 8];
                bl[nt][0] = *(const uint32_t*)&Bl[n * ASTR + ca];
                bl[nt][1] = *(const uint32_t*)&Bl[n * ASTR + ca + 8];
            }
            // A hi fragments
#pragma unroll
            for (int mt = 0; mt < 4; mt++) {
                int r0 = wm + mt * 16 + g;
                af[mt][0] = *(const uint32_t*)&Ah[r0 * ASTR + ca];
                af[mt][1] = *(const uint32_t*)&Ah[(r0 + 8) * ASTR + ca];
                af[mt][2] = *(const uint32_t*)&Ah[r0 * ASTR + ca + 8];
                af[mt][3] = *(const uint32_t*)&Ah[(r0 + 8) * ASTR + ca + 8];
            }
#pragma unroll
            for (int mt = 0; mt < 4; mt++)
#pragma unroll
                for (int nt = 0; nt < 4; nt++) mma16816(acc[mt][nt], af[mt], bh[nt]);
#pragma unroll
            for (int mt = 0; mt < 4; mt++)
#pragma unroll
                for (int nt = 0; nt < 4; nt++) mma16816(acc[mt][nt], af[mt], bl[nt]);
            // A lo fragments (overwrite)
#pragma unroll
            for (int mt = 0; mt < 4; mt++) {
                int r0 = wm + mt * 16 + g;
                af[mt][0] = *(const uint32_t*)&Al[r0 * ASTR + ca];
                af[mt][1] = *(const uint32_t*)&Al[(r0 + 8) * ASTR + ca];
                af[mt][2] = *(const uint32_t*)&Al[r0 * ASTR + ca + 8];
                af[mt][3] = *(const uint32_t*)&Al[(r0 + 8) * ASTR + ca + 8];
            }
#pragma unroll
            for (int mt = 0; mt < 4; mt++)
#pragma unroll
                for (int nt = 0; nt < 4; nt++) mma16816(acc[mt][nt], af[mt], bh[nt]);
        }
        __syncthreads();
    }

    // epilogue
#pragma unroll
    for (int mt = 0; mt < 4; mt++) {
        int r0 = m0 + wm + mt * 16 + g;
        int r1 = r0 + 8;
#pragma unroll
        for (int nt = 0; nt < 4; nt++) {
            int cc = n0 + wn + nt * 8 + t4 * 2;
#pragma unroll
            for (int e = 0; e < 4; e++) {
                int row = (e < 2) ? r0 : r1;
                int col = cc + (e & 1);
                if (row >= M || col >= N) continue;
                float v = acc[mt][nt][e];
                if (bias0) v += bias0[col];
                if (bias1) v += bias1[col];
                if (addsrc) v += addsrc[(size_t)row * N + col];
                C[(size_t)row * N + col] = v;
            }
        }
    }
}

// ------------------------- persistent LSTM scan ----------------------------
#define HSTRIDE 516

__global__ __launch_bounds__(128, 1)
void lstm_persist_kernel(const float* __restrict__ w_hh,
                         const float* __restrict__ xg,
                         float* __restrict__ hbuf,
                         float* __restrict__ hs,
                         int* __restrict__ bar) {
    extern __shared__ float sm[];
    float* ws  = sm;                    // [16][512]
    float* hsm = sm + 16 * 512;         // [32][HSTRIDE]

    int tid  = threadIdx.x;
    int warp = tid >> 5;
    int lane = tid & 31;
    int hd0  = blockIdx.x * HD_PER_BLK;
    int hd   = hd0 + warp;

    for (int idx = tid; idx < 16 * 512; idx += 128) {
        int lr = idx >> 9;
        int k  = idx & 511;
        int hd_l = lr >> 2, gg = lr & 3;
        ws[lr * 512 + k] = w_hh[((size_t)(gg * HDIM + hd0 + hd_l)) * HDIM + k];
    }

    const float* wp = ws + warp * 4 * 512;
    const float* hp = hsm + lane * HSTRIDE;
    float c_reg = 0.f;
    size_t xg_base = ((size_t)lane * TSTEPS) * G4 + hd;

    for (int t = 0; t < TSTEPS; t++) {
        const float* hcur = hbuf + (t & 1) * (BATCH * HDIM);
        float*       hnxt = hbuf + ((t + 1) & 1) * (BATCH * HDIM);

        size_t xb = xg_base + (size_t)t * G4;
        float xgi = __ldg(xg + xb);
        float xgf = __ldg(xg + xb + 512);
        float xgg = __ldg(xg + xb + 1024);
        float xgo = __ldg(xg + xb + 1536);

        if (t > 0) {
            for (int idx = tid; idx < BATCH * HDIM / 4; idx += 128) {
                int b  = idx >> 7;
                int k4 = idx & 127;
                float4 v = ((const float4*)hcur)[idx];
                *(float4*)&hsm[b * HSTRIDE + k4 * 4] = v;
            }
        }
        __syncthreads();

        float ai = 0.f, af = 0.f, ag = 0.f, ao = 0.f;
        if (t > 0) {
#pragma unroll 4
            for (int k4 = 0; k4 < 128; k4++) {
                float4 hv = *(const float4*)(hp + k4 * 4);
                float4 w0 = *(const float4*)(wp + k4 * 4);
                float4 w1 = *(const float4*)(wp + 512 + k4 * 4);
                float4 w2 = *(const float4*)(wp + 1024 + k4 * 4);
                float4 w3 = *(const float4*)(wp + 1536 + k4 * 4);
                ai += w0.x * hv.x + w0.y * hv.y + w0.z * hv.z + w0.w * hv.w;
                af += w1.x * hv.x + w1.y * hv.y + w1.z * hv.z + w1.w * hv.w;
                ag += w2.x * hv.x + w2.y * hv.y + w2.z * hv.z + w2.w * hv.w;
                ao += w3.x * hv.x + w3.y * hv.y + w3.z * hv.z + w3.w * hv.w;
            }
        }
        float i_ = 1.f / (1.f + expf(-(ai + xgi)));
        float f_ = 1.f / (1.f + expf(-(af + xgf)));
        float g_ = tanhf(ag + xgg);
        float o_ = 1.f / (1.f + expf(-(ao + xgo)));
        c_reg = f_ * c_reg + i_ * g_;
        float hn = o_ * tanhf(c_reg);

        hnxt[lane * HDIM + hd] = hn;
        hs[((size_t)(lane * TSTEPS + t)) * HDIM + hd] = hn;

        if (t < TSTEPS - 1) {
            __threadfence();
            __syncthreads();
            if (tid == 0) {
                atomicAdd(&bar[t], 1);
                while (*(volatile int*)&bar[t] < LSTM_NBLK) { }
            }
            __syncthreads();
            __threadfence();
        }
    }
}

// ------------------------- fused attention (kv stride 1024) ----------------
__global__ __launch_bounds__(256)
void attn_kernel(const float* __restrict__ q, const float* __restrict__ kvb,
                 float* __restrict__ ctx) {
    extern __shared__ float sm[];
    float* Ks = sm;                  // 256*65
    float* Vs = Ks + 256 * 65;       // 256*65
    float* qs = Vs + 256 * 65;       // 8*64
    float* ps = qs + 8 * 64;         // 8*256
    int tid = threadIdx.x;
    int b = blockIdx.x >> 3, hh = blockIdx.x & 7;
    const float* kbase = kvb + (size_t)b * SKEYS * 1024 + hh * HEADD;
    const float* vbase = kbase + 512;

    for (int idx = tid; idx < SKEYS * HEADD; idx += 256) {
        int s = idx >> 6, d = idx & 63;
        Ks[s * 65 + d] = kbase[(size_t)s * 1024 + d];
        Vs[s * 65 + d] = vbase[(size_t)s * 1024 + d];
    }
    __syncthreads();

    int w = tid >> 5, l = tid & 31;
    for (int q0 = 0; q0 < TSTEPS; q0 += 8) {
        for (int idx = tid; idx < 8 * HEADD; idx += 256) {
            int qi = idx >> 6, d = idx & 63;
            int qq = q0 + qi;
            qs[idx] = (qq < TSTEPS) ? q[(size_t)(b * TSTEPS + qq) * HDIM + hh * HEADD + d] : 0.f;
        }
        __syncthreads();
        int qq = q0 + w;
        if (qq < TSTEPS) {
            float sc[8];
#pragma unroll
            for (int ki = 0; ki < 8; ki++) {
                int s = l + (ki << 5);
                float dot = 0.f;
#pragma unroll
                for (int d = 0; d < HEADD; d++)
                    dot += qs[w * 64 + d] * Ks[s * 65 + d];
                sc[ki] = dot * 0.125f;
            }
            float m = sc[0];
#pragma unroll
            for (int ki = 1; ki < 8; ki++) m = fmaxf(m, sc[ki]);
#pragma unroll
            for (int o = 16; o > 0; o >>= 1) m = fmaxf(m, __shfl_xor_sync(0xffffffffu, m, o));
            float sum = 0.f;
#pragma unroll
            for (int ki = 0; ki < 8; ki++) { sc[ki] = expf(sc[ki] - m); sum += sc[ki]; }
#pragma unroll
            for (int o = 16; o > 0; o >>= 1) sum += __shfl_xor_sync(0xffffffffu, sum, o);
            float inv = 1.f / sum;
#pragma unroll
            for (int ki = 0; ki < 8; ki++) ps[w * 256 + l + (ki << 5)] = sc[ki] * inv;
            __syncwarp();
            float a0 = 0.f, a1 = 0.f;
#pragma unroll 4
            for (int s = 0; s < SKEYS; s++) {
                float pw = ps[w * 256 + s];
                a0 += pw * Vs[s * 65 + l];
                a1 += pw * Vs[s * 65 + l + 32];
            }
            size_t obase = (size_t)(b * TSTEPS + qq) * HDIM + hh * HEADD;
            ctx[obase + l] = a0;
            ctx[obase + l + 32] = a1;
        }
        __syncthreads();
    }
}

// ------------------------- launch ------------------------------------------
static const int ATTN_SMEM = (2 * 256 * 65 + 8 * 64 + 8 * 256) * (int)sizeof(float);
static const int LSTM_SMEM = (16 * 512 + 32 * HSTRIDE) * (int)sizeof(float);

extern "C" void kernel_launch(void* const* d_in, const int* in_sizes, int n_in,
                              void* d_out, int out_size) {
    const int*   targets    = (const int*)  d_in[0];
    const float* enc        = (const float*)d_in[1];
    const float* embedding  = (const float*)d_in[2];
    const float* w_ih       = (const float*)d_in[3];
    const float* w_hh       = (const float*)d_in[4];
    const float* b_ih       = (const float*)d_in[5];
    const float* b_hh       = (const float*)d_in[6];
    const float* in_proj_w  = (const float*)d_in[7];
    const float* in_proj_b  = (const float*)d_in[8];
    const float* out_proj_w = (const float*)d_in[9];
    const float* out_proj_b = (const float*)d_in[10];
    const float* fc_w       = (const float*)d_in[11];
    const float* fc_b       = (const float*)d_in[12];
    float* out = (float*)d_out;

    float *emb, *xg, *hbuf, *hs, *qb, *kv, *ctx, *comb;
    int* bar;
    cudaGetSymbolAddress((void**)&emb,  d_emb);
    cudaGetSymbolAddress((void**)&xg,   d_xg);
    cudaGetSymbolAddress((void**)&hbuf, d_hbuf);
    cudaGetSymbolAddress((void**)&hs,   d_hs);
    cudaGetSymbolAddress((void**)&qb,   d_q);
    cudaGetSymbolAddress((void**)&kv,   d_kv);
    cudaGetSymbolAddress((void**)&ctx,  d_ctx);
    cudaGetSymbolAddress((void**)&comb, d_comb);
    cudaGetSymbolAddress((void**)&bar,  d_bar);

    cudaFuncSetAttribute(attn_kernel, cudaFuncAttributeMaxDynamicSharedMemorySize, ATTN_SMEM);
    cudaFuncSetAttribute(lstm_persist_kernel, cudaFuncAttributeMaxDynamicSharedMemorySize, LSTM_SMEM);

    // 1. embedding gather (+ barrier reset)
    {
        int n = MROWS * HDIM;
        gather_embed_kernel<<<(n + 255) / 256, 256>>>(targets, embedding, emb, bar);
    }
    // 2. xg = emb @ w_ih^T + b_ih + b_hh
    {
        dim3 grid(G4 / BN, (MROWS + BM - 1) / BM);
        bgemm_tn_kernel<<<grid, 256>>>(emb, w_ih, b_ih, b_hh, nullptr, xg, MROWS, G4, HDIM);
    }
    // 3. LSTM scan (persistent)
    lstm_persist_kernel<<<LSTM_NBLK, 128, LSTM_SMEM>>>(w_hh, xg, hbuf, hs, bar);
    // 4. q projection
    {
        dim3 grid(HDIM / BN, (MROWS + BM - 1) / BM);
        bgemm_tn_kernel<<<grid, 256>>>(hs, in_proj_w, in_proj_b, nullptr, nullptr, qb, MROWS, HDIM, HDIM);
    }
    // 5. k+v projection (single GEMM, N=1024)
    {
        dim3 grid(2 * HDIM / BN, ENCROWS / BM);
        bgemm_tn_kernel<<<grid, 256>>>(enc, in_proj_w + (size_t)HDIM * HDIM,
                                       in_proj_b + HDIM, nullptr, nullptr, kv, ENCROWS, 2 * HDIM, HDIM);
    }
    // 6. attention
    attn_kernel<<<BATCH * NHEADS, 256, ATTN_SMEM>>>(qb, kv, ctx);
    // 7. out projection + residual (lstm_out)
    {
        dim3 grid(HDIM / BN, (MROWS + BM - 1) / BM);
        bgemm_tn_kernel<<<grid, 256>>>(ctx, out_proj_w, out_proj_b, nullptr, hs, comb, MROWS, HDIM, HDIM);
    }
    // 8. fc
    {
        dim3 grid((VOCAB + BN - 1) / BN, (MROWS + BM - 1) / BM);
        bgemm_tn_kernel<<<grid, 256>>>(comb, fc_w, fc_b, nullptr, nullptr, out, MROWS, VOCAB, HDIM);
    }
}

// round 5
// speedup vs baseline: 1.4024x; 1.1434x over previous
#include <cuda_runtime.h>
#include <cuda_bf16.h>
#include <math.h>
#include <stdint.h>

// Problem constants
#define BATCH 32
#define LSEQ  128
#define TSTEPS 127
#define HDIM  512
#define VOCAB 8000
#define NHEADS 8
#define HEADD 64
#define SKEYS 256
#define G4    2048
#define MROWS (BATCH*TSTEPS)   // 4064
#define ENCROWS (BATCH*SKEYS)  // 8192

#define LSTM_NBLK 128
#define HD_PER_BLK 4

typedef __nv_bfloat16 bf16;

// ------------------------- scratch (device globals) -------------------------
__device__ float d_xg  [MROWS * G4];
__device__ float d_hbuf[2 * BATCH * HDIM];
__device__ float d_hs  [MROWS * HDIM];
__device__ float d_q   [MROWS * HDIM];
__device__ float d_kv  [ENCROWS * 2 * HDIM];
__device__ int   d_bar [TSTEPS];

// bf16 hi/lo operand buffers
__device__ bf16 d_eh [MROWS * HDIM],    d_el [MROWS * HDIM];      // emb
__device__ bf16 d_hsh[MROWS * HDIM],    d_hsl[MROWS * HDIM];      // lstm out
__device__ bf16 d_ch [MROWS * HDIM],    d_cl [MROWS * HDIM];      // ctx
__device__ bf16 d_cbh[MROWS * HDIM],    d_cbl[MROWS * HDIM];      // combined
__device__ bf16 d_enh[ENCROWS * HDIM],  d_enl[ENCROWS * HDIM];    // encoder
__device__ bf16 d_wih[G4 * HDIM],       d_wil[G4 * HDIM];         // w_ih
__device__ bf16 d_iph[3 * HDIM * HDIM], d_ipl[3 * HDIM * HDIM];   // in_proj
__device__ bf16 d_oph[HDIM * HDIM],     d_opl[HDIM * HDIM];       // out_proj
__device__ bf16 d_fch[VOCAB * HDIM],    d_fcl[VOCAB * HDIM];      // fc_w

// ------------------------- helpers ------------------------------------------
__device__ __forceinline__ void split2(float v, bf16& h, bf16& l) {
    h = __float2bfloat16_rn(v);
    l = __float2bfloat16_rn(v - __bfloat162float(h));
}

__device__ __forceinline__ void cp_async16(uint32_t dst, const void* src, int szz) {
    asm volatile("cp.async.cg.shared.global [%0], [%1], 16, %2;" :: "r"(dst), "l"(src), "r"(szz));
}
__device__ __forceinline__ void cp_commit() { asm volatile("cp.async.commit_group;"); }
template<int NW> __device__ __forceinline__ void cp_wait() {
    asm volatile("cp.async.wait_group %0;" :: "n"(NW));
}

// ------------------------- fp32 -> bf16 hi/lo conversion --------------------
__global__ void cvt_kernel(const float* __restrict__ x, bf16* __restrict__ h,
                           bf16* __restrict__ l, int n4) {
    int i = blockIdx.x * blockDim.x + threadIdx.x;
    if (i >= n4) return;
    float4 v = ((const float4*)x)[i];
    bf16 hh[4], ll[4];
    split2(v.x, hh[0], ll[0]); split2(v.y, hh[1], ll[1]);
    split2(v.z, hh[2], ll[2]); split2(v.w, hh[3], ll[3]);
    ((uint2*)h)[i] = *(uint2*)hh;
    ((uint2*)l)[i] = *(uint2*)ll;
}

// ------------------------- embedding gather (split output) -----------------
__global__ void gather_embed_kernel(const int* __restrict__ targets,
                                    const float* __restrict__ embedding,
                                    bf16* __restrict__ eh, bf16* __restrict__ el,
                                    int* __restrict__ bar) {
    int idx = blockIdx.x * blockDim.x + threadIdx.x;
    if (idx < TSTEPS) bar[idx] = 0;
    if (idx >= MROWS * HDIM) return;
    int hh = idx & (HDIM - 1);
    int bt = idx >> 9;
    int b = bt / TSTEPS;
    int t = bt - b * TSTEPS;
    int tok = targets[b * LSEQ + t];
    float v = embedding[(size_t)tok * HDIM + hh];
    bf16 h, l; split2(v, h, l);
    eh[idx] = h; el[idx] = l;
}

// ------------------------- split-bf16 mma GEMM, cp.async 2-stage ------------
// C[M,N] = A[M,K] @ B[N,K]^T with A,B given as bf16 hi/lo pairs.
// acc = Ah*Bh + Ah*Bl + Al*Bh. Block 128x128x32, 8 warps, warp 64x32.
// Output: fp32 C, or split bf16 (Ch,Cl) if Ch != nullptr.
#define BM 128
#define BN 128
#define BK 32
#define ASTR 40                  // bf16/row in smem (80B stride, conflict-free)
#define STILE (128 * ASTR)       // elems per tile
#define SSTAGE (4 * STILE)       // elems per stage (Ah,Al,Bh,Bl)
#define GEMM_SMEM (2 * SSTAGE * 2)   // bytes

__device__ __forceinline__ void mma16816(float* c, const uint32_t a[4], const uint32_t b[2]) {
    asm volatile(
        "mma.sync.aligned.m16n8k16.row.col.f32.bf16.bf16.f32 "
        "{%0,%1,%2,%3}, {%4,%5,%6,%7}, {%8,%9}, {%0,%1,%2,%3};"
        : "+f"(c[0]), "+f"(c[1]), "+f"(c[2]), "+f"(c[3])
        : "r"(a[0]), "r"(a[1]), "r"(a[2]), "r"(a[3]), "r"(b[0]), "r"(b[1]));
}

__global__ __launch_bounds__(256)
void bgemm2_kernel(const bf16* __restrict__ Ahg, const bf16* __restrict__ Alg,
                   const bf16* __restrict__ Bhg, const bf16* __restrict__ Blg,
                   const float* __restrict__ bias0, const float* __restrict__ bias1,
                   const float* __restrict__ addsrc,
                   float* __restrict__ C, bf16* __restrict__ Ch, bf16* __restrict__ Cl,
                   int M, int N, int K) {
    extern __shared__ bf16 smem[];
    uint32_t sbase = (uint32_t)__cvta_generic_to_shared(smem);

    int tid = threadIdx.x;
    int m0 = blockIdx.y * BM, n0 = blockIdx.x * BN;
    int warp = tid >> 5, lane = tid & 31;
    int wm = (warp >> 2) * 64;
    int wn = (warp & 3) * 32;
    int g  = lane >> 2;
    int t4 = lane & 3;
    int NIT = K / BK;

    // per-thread load slots: 2 chunks (16B) per tile, 4 tiles
    int cid0 = tid * 2, cid1 = tid * 2 + 1;
    int r0c = cid0 >> 2, c0c = cid0 & 3;
    int r1c = cid1 >> 2, c1c = cid1 & 3;

    float acc[4][4][4];
#pragma unroll
    for (int i = 0; i < 4; i++)
#pragma unroll
        for (int j = 0; j < 4; j++) {
            acc[i][j][0] = 0.f; acc[i][j][1] = 0.f; acc[i][j][2] = 0.f; acc[i][j][3] = 0.f;
        }

    // tile loader
    auto load_stage = [&](int s, int k0) {
        uint32_t so = sbase + (uint32_t)(s * SSTAGE) * 2;
#pragma unroll
        for (int t = 0; t < 4; t++) {
            const bf16* gp = (t == 0) ? Ahg : (t == 1) ? Alg : (t == 2) ? Bhg : Blg;
            int rb  = (t < 2) ? m0 : n0;
            int lim = (t < 2) ? M : N;
            int gr0 = rb + r0c; int v0 = (gr0 < lim) ? 16 : 0; if (gr0 >= lim) gr0 = lim - 1;
            int gr1 = rb + r1c; int v1 = (gr1 < lim) ? 16 : 0; if (gr1 >= lim) gr1 = lim - 1;
            cp_async16(so + (uint32_t)(t * STILE + r0c * ASTR + c0c * 8) * 2,
                       gp + (size_t)gr0 * K + k0 + c0c * 8, v0);
            cp_async16(so + (uint32_t)(t * STILE + r1c * ASTR + c1c * 8) * 2,
                       gp + (size_t)gr1 * K + k0 + c1c * 8, v1);
        }
    };

    load_stage(0, 0);
    cp_commit();

    for (int it = 0; it < NIT; it++) {
        if (it + 1 < NIT) {
            load_stage((it + 1) & 1, (it + 1) * BK);
            cp_commit();
            cp_wait<1>();
        } else {
            cp_wait<0>();
        }
        __syncthreads();

        const bf16* Ah = smem + (it & 1) * SSTAGE;
        const bf16* Al = Ah + STILE;
        const bf16* Bh = Al + STILE;
        const bf16* Bl = Bh + STILE;

#pragma unroll
        for (int ko = 0; ko < BK; ko += 16) {
            uint32_t af[4][4], bh[4][2], bl[4][2];
            int ca = ko + t4 * 2;
#pragma unroll
            for (int nt = 0; nt < 4; nt++) {
                int n = wn + nt * 8 + g;
                bh[nt][0] = *(const uint32_t*)&Bh[n * ASTR + ca];
                bh[nt][1] = *(const uint32_t*)&Bh[n * ASTR + ca + 8];
                bl[nt][0] = *(const uint32_t*)&Bl[n * ASTR + ca];
                bl[nt][1] = *(const uint32_t*)&Bl[n * ASTR + ca + 8];
            }
#pragma unroll
            for (int mt = 0; mt < 4; mt++) {
                int r = wm + mt * 16 + g;
                af[mt][0] = *(const uint32_t*)&Ah[r * ASTR + ca];
                af[mt][1] = *(const uint32_t*)&Ah[(r + 8) * ASTR + ca];
                af[mt][2] = *(const uint32_t*)&Ah[r * ASTR + ca + 8];
                af[mt][3] = *(const uint32_t*)&Ah[(r + 8) * ASTR + ca + 8];
            }
#pragma unroll
            for (int mt = 0; mt < 4; mt++)
#pragma unroll
                for (int nt = 0; nt < 4; nt++) mma16816(acc[mt][nt], af[mt], bh[nt]);
#pragma unroll
            for (int mt = 0; mt < 4; mt++)
#pragma unroll
                for (int nt = 0; nt < 4; nt++) mma16816(acc[mt][nt], af[mt], bl[nt]);
#pragma unroll
            for (int mt = 0; mt < 4; mt++) {
                int r = wm + mt * 16 + g;
                af[mt][0] = *(const uint32_t*)&Al[r * ASTR + ca];
                af[mt][1] = *(const uint32_t*)&Al[(r + 8) * ASTR + ca];
                af[mt][2] = *(const uint32_t*)&Al[r * ASTR + ca + 8];
                af[mt][3] = *(const uint32_t*)&Al[(r + 8) * ASTR + ca + 8];
            }
#pragma unroll
            for (int mt = 0; mt < 4; mt++)
#pragma unroll
                for (int nt = 0; nt < 4; nt++) mma16816(acc[mt][nt], af[mt], bh[nt]);
        }
        __syncthreads();
    }

    // epilogue
#pragma unroll
    for (int mt = 0; mt < 4; mt++) {
        int rr0 = m0 + wm + mt * 16 + g;
        int rr1 = rr0 + 8;
#pragma unroll
        for (int nt = 0; nt < 4; nt++) {
            int cc = n0 + wn + nt * 8 + t4 * 2;
#pragma unroll
            for (int e = 0; e < 4; e++) {
                int row = (e < 2) ? rr0 : rr1;
                int col = cc + (e & 1);
                if (row >= M || col >= N) continue;
                float v = acc[mt][nt][e];
                if (bias0) v += bias0[col];
                if (bias1) v += bias1[col];
                if (addsrc) v += addsrc[(size_t)row * N + col];
                if (Ch) {
                    bf16 h, l; split2(v, h, l);
                    Ch[(size_t)row * N + col] = h;
                    Cl[(size_t)row * N + col] = l;
                } else {
                    C[(size_t)row * N + col] = v;
                }
            }
        }
    }
}

// ------------------------- persistent LSTM scan ----------------------------
#define HSTRIDE 516

__global__ __launch_bounds__(128, 1)
void lstm_persist_kernel(const float* __restrict__ w_hh,
                         const float* __restrict__ xg,
                         float* __restrict__ hbuf,
                         float* __restrict__ hs,
                         bf16* __restrict__ hsh, bf16* __restrict__ hsl,
                         int* __restrict__ bar) {
    extern __shared__ float sm[];
    float* ws  = sm;                    // [16][512]
    float* hsm = sm + 16 * 512;         // [32][HSTRIDE]

    int tid  = threadIdx.x;
    int warp = tid >> 5;
    int lane = tid & 31;
    int hd0  = blockIdx.x * HD_PER_BLK;
    int hd   = hd0 + warp;

    for (int idx = tid; idx < 16 * 512; idx += 128) {
        int lr = idx >> 9;
        int k  = idx & 511;
        int hd_l = lr >> 2, gg = lr & 3;
        ws[lr * 512 + k] = w_hh[((size_t)(gg * HDIM + hd0 + hd_l)) * HDIM + k];
    }

    const float* wp = ws + warp * 4 * 512;
    const float* hp = hsm + lane * HSTRIDE;
    float c_reg = 0.f;
    size_t xg_base = ((size_t)lane * TSTEPS) * G4 + hd;

    for (int t = 0; t < TSTEPS; t++) {
        const float* hcur = hbuf + (t & 1) * (BATCH * HDIM);
        float*       hnxt = hbuf + ((t + 1) & 1) * (BATCH * HDIM);

        size_t xb = xg_base + (size_t)t * G4;
        float xgi = __ldg(xg + xb);
        float xgf = __ldg(xg + xb + 512);
        float xgg = __ldg(xg + xb + 1024);
        float xgo = __ldg(xg + xb + 1536);

        if (t > 0) {
            for (int idx = tid; idx < BATCH * HDIM / 4; idx += 128) {
                int b  = idx >> 7;
                int k4 = idx & 127;
                float4 v = ((const float4*)hcur)[idx];
                *(float4*)&hsm[b * HSTRIDE + k4 * 4] = v;
            }
        }
        __syncthreads();

        float ai = 0.f, af = 0.f, ag = 0.f, ao = 0.f;
        if (t > 0) {
#pragma unroll 4
            for (int k4 = 0; k4 < 128; k4++) {
                float4 hv = *(const float4*)(hp + k4 * 4);
                float4 w0 = *(const float4*)(wp + k4 * 4);
                float4 w1 = *(const float4*)(wp + 512 + k4 * 4);
                float4 w2 = *(const float4*)(wp + 1024 + k4 * 4);
                float4 w3 = *(const float4*)(wp + 1536 + k4 * 4);
                ai += w0.x * hv.x + w0.y * hv.y + w0.z * hv.z + w0.w * hv.w;
                af += w1.x * hv.x + w1.y * hv.y + w1.z * hv.z + w1.w * hv.w;
                ag += w2.x * hv.x + w2.y * hv.y + w2.z * hv.z + w2.w * hv.w;
                ao += w3.x * hv.x + w3.y * hv.y + w3.z * hv.z + w3.w * hv.w;
            }
        }
        float i_ = 1.f / (1.f + expf(-(ai + xgi)));
        float f_ = 1.f / (1.f + expf(-(af + xgf)));
        float g_ = tanhf(ag + xgg);
        float o_ = 1.f / (1.f + expf(-(ao + xgo)));
        c_reg = f_ * c_reg + i_ * g_;
        float hn = o_ * tanhf(c_reg);

        hnxt[lane * HDIM + hd] = hn;
        size_t hsi = ((size_t)(lane * TSTEPS + t)) * HDIM + hd;
        hs[hsi] = hn;
        bf16 hh, hl; split2(hn, hh, hl);
        hsh[hsi] = hh; hsl[hsi] = hl;

        if (t < TSTEPS - 1) {
            __threadfence();
            __syncthreads();
            if (tid == 0) {
                atomicAdd(&bar[t], 1);
                while (*(volatile int*)&bar[t] < LSTM_NBLK) { }
            }
            __syncthreads();
            __threadfence();
        }
    }
}

// ------------------------- fused attention (split bf16 output) -------------
__global__ __launch_bounds__(256)
void attn_kernel(const float* __restrict__ q, const float* __restrict__ kvb,
                 bf16* __restrict__ ch, bf16* __restrict__ cl) {
    extern __shared__ float sm[];
    float* Ks = sm;                  // 256*65
    float* Vs = Ks + 256 * 65;       // 256*65
    float* qs = Vs + 256 * 65;       // 8*64
    float* ps = qs + 8 * 64;         // 8*256
    int tid = threadIdx.x;
    int b = blockIdx.x >> 3, hh = blockIdx.x & 7;
    const float* kbase = kvb + (size_t)b * SKEYS * 1024 + hh * HEADD;
    const float* vbase = kbase + 512;

    for (int idx = tid; idx < SKEYS * HEADD; idx += 256) {
        int s = idx >> 6, d = idx & 63;
        Ks[s * 65 + d] = kbase[(size_t)s * 1024 + d];
        Vs[s * 65 + d] = vbase[(size_t)s * 1024 + d];
    }
    __syncthreads();

    int w = tid >> 5, l = tid & 31;
    for (int q0 = 0; q0 < TSTEPS; q0 += 8) {
        for (int idx = tid; idx < 8 * HEADD; idx += 256) {
            int qi = idx >> 6, d = idx & 63;
            int qq = q0 + qi;
            qs[idx] = (qq < TSTEPS) ? q[(size_t)(b * TSTEPS + qq) * HDIM + hh * HEADD + d] : 0.f;
        }
        __syncthreads();
        int qq = q0 + w;
        if (qq < TSTEPS) {
            float sc[8];
#pragma unroll
            for (int ki = 0; ki < 8; ki++) {
                int s = l + (ki << 5);
                float dot = 0.f;
#pragma unroll
                for (int d = 0; d < HEADD; d++)
                    dot += qs[w * 64 + d] * Ks[s * 65 + d];
                sc[ki] = dot * 0.125f;
            }
            float m = sc[0];
#pragma unroll
            for (int ki = 1; ki < 8; ki++) m = fmaxf(m, sc[ki]);
#pragma unroll
            for (int o = 16; o > 0; o >>= 1) m = fmaxf(m, __shfl_xor_sync(0xffffffffu, m, o));
            float sum = 0.f;
#pragma unroll
            for (int ki = 0; ki < 8; ki++) { sc[ki] = expf(sc[ki] - m); sum += sc[ki]; }
#pragma unroll
            for (int o = 16; o > 0; o >>= 1) sum += __shfl_xor_sync(0xffffffffu, sum, o);
            float inv = 1.f / sum;
#pragma unroll
            for (int ki = 0; ki < 8; ki++) ps[w * 256 + l + (ki << 5)] = sc[ki] * inv;
            __syncwarp();
            float a0 = 0.f, a1 = 0.f;
#pragma unroll 4
            for (int s = 0; s < SKEYS; s++) {
                float pw = ps[w * 256 + s];
                a0 += pw * Vs[s * 65 + l];
                a1 += pw * Vs[s * 65 + l + 32];
            }
            size_t obase = (size_t)(b * TSTEPS + qq) * HDIM + hh * HEADD;
            bf16 h0, l0, h1, l1;
            split2(a0, h0, l0); split2(a1, h1, l1);
            ch[obase + l] = h0;      cl[obase + l] = l0;
            ch[obase + l + 32] = h1; cl[obase + l + 32] = l1;
        }
        __syncthreads();
    }
}

// ------------------------- launch ------------------------------------------
static const int ATTN_SMEM = (2 * 256 * 65 + 8 * 64 + 8 * 256) * (int)sizeof(float);
static const int LSTM_SMEM = (16 * 512 + 32 * HSTRIDE) * (int)sizeof(float);

extern "C" void kernel_launch(void* const* d_in, const int* in_sizes, int n_in,
                              void* d_out, int out_size) {
    const int*   targets    = (const int*)  d_in[0];
    const float* enc        = (const float*)d_in[1];
    const float* embedding  = (const float*)d_in[2];
    const float* w_ih       = (const float*)d_in[3];
    const float* w_hh       = (const float*)d_in[4];
    const float* b_ih       = (const float*)d_in[5];
    const float* b_hh       = (const float*)d_in[6];
    const float* in_proj_w  = (const float*)d_in[7];
    const float* in_proj_b  = (const float*)d_in[8];
    const float* out_proj_w = (const float*)d_in[9];
    const float* out_proj_b = (const float*)d_in[10];
    const float* fc_w       = (const float*)d_in[11];
    const float* fc_b       = (const float*)d_in[12];
    float* out = (float*)d_out;

    float *xg, *hbuf, *hs, *qb, *kv;
    int* bar;
    bf16 *eh, *el, *hsh, *hsl, *ch, *cl, *cbh, *cbl, *enh, *enl;
    bf16 *wih, *wil, *iph, *ipl, *oph, *opl, *fch, *fcl;
    cudaGetSymbolAddress((void**)&xg,   d_xg);
    cudaGetSymbolAddress((void**)&hbuf, d_hbuf);
    cudaGetSymbolAddress((void**)&hs,   d_hs);
    cudaGetSymbolAddress((void**)&qb,   d_q);
    cudaGetSymbolAddress((void**)&kv,   d_kv);
    cudaGetSymbolAddress((void**)&bar,  d_bar);
    cudaGetSymbolAddress((void**)&eh,  d_eh);  cudaGetSymbolAddress((void**)&el,  d_el);
    cudaGetSymbolAddress((void**)&hsh, d_hsh); cudaGetSymbolAddress((void**)&hsl, d_hsl);
    cudaGetSymbolAddress((void**)&ch,  d_ch);  cudaGetSymbolAddress((void**)&cl,  d_cl);
    cudaGetSymbolAddress((void**)&cbh, d_cbh); cudaGetSymbolAddress((void**)&cbl, d_cbl);
    cudaGetSymbolAddress((void**)&enh, d_enh); cudaGetSymbolAddress((void**)&enl, d_enl);
    cudaGetSymbolAddress((void**)&wih, d_wih); cudaGetSymbolAddress((void**)&wil, d_wil);
    cudaGetSymbolAddress((void**)&iph, d_iph); cudaGetSymbolAddress((void**)&ipl, d_ipl);
    cudaGetSymbolAddress((void**)&oph, d_oph); cudaGetSymbolAddress((void**)&opl, d_opl);
    cudaGetSymbolAddress((void**)&fch, d_fch); cudaGetSymbolAddress((void**)&fcl, d_fcl);

    cudaFuncSetAttribute(attn_kernel, cudaFuncAttributeMaxDynamicSharedMemorySize, ATTN_SMEM);
    cudaFuncSetAttribute(lstm_persist_kernel, cudaFuncAttributeMaxDynamicSharedMemorySize, LSTM_SMEM);
    cudaFuncSetAttribute(bgemm2_kernel, cudaFuncAttributeMaxDynamicSharedMemorySize, GEMM_SMEM);

    // 1. gather + convert inputs
    {
        int n = MROWS * HDIM;
        gather_embed_kernel<<<(n + 255) / 256, 256>>>(targets, embedding, eh, el, bar);
    }
    cvt_kernel<<<(G4 * HDIM / 4 + 255) / 256, 256>>>(w_ih, wih, wil, G4 * HDIM / 4);
    cvt_kernel<<<(3 * HDIM * HDIM / 4 + 255) / 256, 256>>>(in_proj_w, iph, ipl, 3 * HDIM * HDIM / 4);
    cvt_kernel<<<(HDIM * HDIM / 4 + 255) / 256, 256>>>(out_proj_w, oph, opl, HDIM * HDIM / 4);
    cvt_kernel<<<(VOCAB * HDIM / 4 + 255) / 256, 256>>>(fc_w, fch, fcl, VOCAB * HDIM / 4);
    cvt_kernel<<<(ENCROWS * HDIM / 4 + 255) / 256, 256>>>(enc, enh, enl, ENCROWS * HDIM / 4);

    // 2. xg = emb @ w_ih^T + b_ih + b_hh
    {
        dim3 grid(G4 / BN, (MROWS + BM - 1) / BM);
        bgemm2_kernel<<<grid, 256, GEMM_SMEM>>>(eh, el, wih, wil, b_ih, b_hh, nullptr,
                                                xg, nullptr, nullptr, MROWS, G4, HDIM);
    }
    // 3. LSTM scan
    lstm_persist_kernel<<<LSTM_NBLK, 128, LSTM_SMEM>>>(w_hh, xg, hbuf, hs, hsh, hsl, bar);
    // 4. q projection
    {
        dim3 grid(HDIM / BN, (MROWS + BM - 1) / BM);
        bgemm2_kernel<<<grid, 256, GEMM_SMEM>>>(hsh, hsl, iph, ipl, in_proj_b, nullptr, nullptr,
                                                qb, nullptr, nullptr, MROWS, HDIM, HDIM);
    }
    // 5. k+v projection (N=1024)
    {
        dim3 grid(2 * HDIM / BN, ENCROWS / BM);
        bgemm2_kernel<<<grid, 256, GEMM_SMEM>>>(enh, enl,
                                                iph + (size_t)HDIM * HDIM, ipl + (size_t)HDIM * HDIM,
                                                in_proj_b + HDIM, nullptr, nullptr,
                                                kv, nullptr, nullptr, ENCROWS, 2 * HDIM, HDIM);
    }
    // 6. attention -> split ctx
    attn_kernel<<<BATCH * NHEADS, 256, ATTN_SMEM>>>(qb, kv, ch, cl);
    // 7. out projection + residual -> split combined
    {
        dim3 grid(HDIM / BN, (MROWS + BM - 1) / BM);
        bgemm2_kernel<<<grid, 256, GEMM_SMEM>>>(ch, cl, oph, opl, out_proj_b, nullptr, hs,
                                                nullptr, cbh, cbl, MROWS, HDIM, HDIM);
    }
    // 8. fc
    {
        dim3 grid((VOCAB + BN - 1) / BN, (MROWS + BM - 1) / BM);
        bgemm2_kernel<<<grid, 256, GEMM_SMEM>>>(cbh, cbl, fch, fcl, fc_b, nullptr, nullptr,
                                                out, nullptr, nullptr, MROWS, VOCAB, HDIM);
    }
}